// round 13
// baseline (speedup 1.0000x reference)
#include <cuda_runtime.h>
#include <cuda_bf16.h>
#include <cstdint>

// ============================================================================
// Simplicial attention, single-pass linearized, uniform 64-tile jobs.
// 512 threads/CTA, 64-reg budget -> 2 CTAs/SM = 32 warps/SM (2x latency hiding).
//   S:  16 warps as 4m x 4n grid, warp tile m16 x n16 (d = 8 regs)
//   PV: 16 warps as 2m x 8n grid, warp tile m32 x n32 (acc = 32 regs)
// Math identical to R11 (order-1 linearized double softmax, exact src0 diag).
// ============================================================================

#define D      256
#define QR     64
#define KT     64
#define NT     64
#define NTH    512
#define NQ     8192
#define SCALE  0.0625f
#define QLD    264
#define KLD    264
#define ULD    72

#define SQ_OFF  0
#define SQ_SZ   (QR * QLD * 2)            // 33792
#define K_OFF   SQ_SZ
#define K_SZ    (KT * KLD * 2)            // 33792 x2
#define U_OFF   (K_OFF + 2 * K_SZ)        // 101376
#define U_SZ    (QR * ULD * 2)            // 9216
#define SMEM_TOTAL (U_OFF + U_SZ)         // 110592 -> 2 CTAs/SM

// ---------------------------------------------------------------------------
__device__ __align__(128) __nv_bfloat16 g_kv[28672 * 256];   // 14.7 MB
__device__ __align__(128) float    g_vsum[3 * 256];
__device__ __align__(128) uint32_t g_mb1[8192L * 128];       // 4 MB, B_low^T bits
__device__ __align__(128) float    g_T1[3L * 8192 * 256];    // 25 MB partials
__device__ __align__(128) float    g_Z[3 * 8192];
__device__ __align__(128) float    g_t1[3 * 8192];
__device__ __align__(128) float    g_eii[8192];              // masked diag e

__device__ __forceinline__ uint32_t smem_u32(const void* p) {
    return (uint32_t)__cvta_generic_to_shared(p);
}
__device__ __forceinline__ void cp16(uint32_t dst, const void* src) {
    asm volatile("cp.async.cg.shared.global [%0], [%1], 16;" :: "r"(dst), "l"(src));
}
#define CP_COMMIT() asm volatile("cp.async.commit_group;" ::: "memory")
#define CP_WAIT1()  asm volatile("cp.async.wait_group 1;" ::: "memory")

__device__ __forceinline__ void ldsm_x4(uint32_t& r0, uint32_t& r1,
                                        uint32_t& r2, uint32_t& r3, uint32_t addr) {
    asm volatile("ldmatrix.sync.aligned.m8n8.x4.shared.b16 {%0,%1,%2,%3}, [%4];\n"
                 : "=r"(r0), "=r"(r1), "=r"(r2), "=r"(r3) : "r"(addr));
}
__device__ __forceinline__ void ldsm_x4_t(uint32_t& r0, uint32_t& r1,
                                          uint32_t& r2, uint32_t& r3, uint32_t addr) {
    asm volatile("ldmatrix.sync.aligned.m8n8.x4.trans.shared.b16 {%0,%1,%2,%3}, [%4];\n"
                 : "=r"(r0), "=r"(r1), "=r"(r2), "=r"(r3) : "r"(addr));
}
__device__ __forceinline__ void mma_bf16(float* d, const uint32_t* a, const uint32_t* b) {
    asm volatile(
        "mma.sync.aligned.m16n8k16.row.col.f32.bf16.bf16.f32 "
        "{%0,%1,%2,%3}, {%4,%5,%6,%7}, {%8,%9}, {%0,%1,%2,%3};\n"
        : "+f"(d[0]), "+f"(d[1]), "+f"(d[2]), "+f"(d[3])
        : "r"(a[0]), "r"(a[1]), "r"(a[2]), "r"(a[3]), "r"(b[0]), "r"(b[1]));
}

// ---------------------------------------------------------------------------
__global__ void init_kernel() {
    long idx = (long)blockIdx.x * 256 + threadIdx.x;
    if (idx < 3L * 8192 * 256) g_T1[idx] = 0.0f;
    if (idx < 3 * 8192) { g_Z[idx] = 0.0f; g_t1[idx] = 0.0f; }
    if (idx < 8192) g_eii[idx] = 0.0f;
    if (idx < 3 * 256) g_vsum[idx] = 0.0f;
}

__global__ void convert_kernel(const float* __restrict__ H,
                               const float* __restrict__ Hlow,
                               const float* __restrict__ Hhigh) {
    int r0 = blockIdx.x * 32, col = threadIdx.x;
    float acc = 0.0f;
    #pragma unroll 4
    for (int i = 0; i < 32; i++) {
        int r = r0 + i;
        float v;
        if (r < 8192)       v = H[(long)r * D + col];
        else if (r < 12288) v = Hlow[(long)(r - 8192) * D + col];
        else                v = Hhigh[(long)(r - 12288) * D + col];
        g_kv[(long)r * D + col] = __float2bfloat16(v);
        acc += v;
    }
    int src = (r0 < 8192) ? 0 : (r0 < 12288 ? 1 : 2);
    atomicAdd(&g_vsum[src * 256 + col], acc);
}

// pack B_low[4096][8192] transposed -> g_mb1[8192 rows][128 words]
__global__ void pack_T_kernel(const int* __restrict__ B) {
    __shared__ int sm[32 * 33];
    int kt = blockIdx.x & 127, it = blockIdx.x >> 7;
    int k0 = kt * 32, i0 = it * 32;
    int tid = threadIdx.x;
    #pragma unroll
    for (int s = 0; s < 4; s++) {
        int idx = tid + s * 256;
        int r = idx >> 5, c = idx & 31;
        sm[r * 33 + c] = B[(long)(k0 + r) * NQ + i0 + c];
    }
    __syncthreads();
    int w = tid >> 5, lane = tid & 31;
    #pragma unroll
    for (int q = 0; q < 4; q++) {
        int i = w * 4 + q;
        uint32_t word = __ballot_sync(0xffffffffu, sm[lane * 33 + i] != 0);
        if (lane == 0) g_mb1[(long)(i0 + i) * 128 + kt] = word;
    }
}

// ---------------------------------------------------------------------------
__global__ __launch_bounds__(NTH, 2)
void attn_kernel(const int* __restrict__ L,
                 const int* __restrict__ Bhigh) {
    extern __shared__ char smem[];
    uint32_t sb = smem_u32(smem);
    const uint32_t sQ = sb + SQ_OFF;
    __nv_bfloat16* sUp = (__nv_bfloat16*)(smem + U_OFF);

    int bid = blockIdx.x;
    int qt = bid / 7, ch = bid % 7;
    int i0 = qt * QR;

    int src, kvrow0, kloc0, W;
    const int* mask;
    if (ch < 2)      { src = 0; kvrow0 = ch * 4096;            kloc0 = ch * 4096;     W = 8192;  mask = L; }
    else if (ch == 2){ src = 1; kvrow0 = 8192;                 kloc0 = 0;             W = 0;     mask = L; }
    else             { src = 2; kvrow0 = 12288 + (ch-3)*4096;  kloc0 = (ch-3)*4096;   W = 16384; mask = Bhigh; }
    int diag_j = -1;
    if (src == 0) { int dj = (i0 - kloc0) >> 6; if (dj >= 0 && dj < NT) diag_j = dj; }

    int tid = threadIdx.x, lane = tid & 31, w = tid >> 5;
    // S grid: 4m x 4n, warp m16 x n16
    int smi = w & 3, sni = w >> 2;
    // PV grid: 2m x 8n, warp m32 x n32
    int pmi = w & 1, pni = w >> 1;
    int g = lane >> 2, c2 = (lane & 3) << 1;
    int lr16 = lane & 15, lc8 = (lane >> 4) << 3;
    int brow = (lane & 7) + ((lane & 16) >> 1), bcol8 = lane & 8;
    int m0 = smi * 16 + g;

    // ---- prologue: Q + K0 group, K1 group
    {
        const char* gq = (const char*)(g_kv + (long)i0 * D);
        #pragma unroll
        for (int i = 0; i < 4; i++) {
            int idx = tid + i * NTH;                  // 2048 chunks
            int r = idx >> 5, cc = (idx & 31) << 3;
            cp16(sQ + (uint32_t)((r * QLD + cc) * 2), gq + ((long)r * D + cc) * 2);
        }
        const char* gk = (const char*)(g_kv + (long)kvrow0 * D);
        #pragma unroll
        for (int i = 0; i < 4; i++) {
            int idx = tid + i * NTH;
            int k = idx >> 5, cc = (idx & 31) << 3;
            cp16(sb + K_OFF + (uint32_t)((k * KLD + cc) * 2), gk + ((long)k * D + cc) * 2);
        }
        CP_COMMIT();
        const char* gk1 = (const char*)(g_kv + (long)(kvrow0 + KT) * D);
        #pragma unroll
        for (int i = 0; i < 4; i++) {
            int idx = tid + i * NTH;
            int k = idx >> 5, cc = (idx & 31) << 3;
            cp16(sb + K_OFF + K_SZ + (uint32_t)((k * KLD + cc) * 2), gk1 + ((long)k * D + cc) * 2);
        }
        CP_COMMIT();
    }

    float zacc0 = 0.f, zacc1 = 0.f, t1acc0 = 0.f, t1acc1 = 0.f;
    float acc[8][4];
    #pragma unroll
    for (int f = 0; f < 8; f++) { acc[f][0]=0.f; acc[f][1]=0.f; acc[f][2]=0.f; acc[f][3]=0.f; }

    uint32_t aBase = sQ + (uint32_t)(((smi * 16 + lr16) * QLD + lc8) * 2);
    uint32_t sUo = sb + U_OFF;
    const int* mr0 = mask + (long)(i0 + m0) * W + kloc0 + sni * 16 + c2;
    const int* mr1 = mask + (long)(i0 + m0 + 8) * W + kloc0 + sni * 16 + c2;
    const uint32_t* br0 = g_mb1 + (long)(i0 + m0) * 128;
    const uint32_t* br1 = g_mb1 + (long)(i0 + m0 + 8) * 128;

    for (int j = 0; j < NT; j++) {
        CP_WAIT1();
        __syncthreads();
        uint32_t kb = sb + K_OFF + (j & 1) * K_SZ;

        // ---- S = Q K^T: warp m16 x n16 (subset of proven path)
        float d[2][4];
        d[0][0]=0.f; d[0][1]=0.f; d[0][2]=0.f; d[0][3]=0.f;
        d[1][0]=0.f; d[1][1]=0.f; d[1][2]=0.f; d[1][3]=0.f;
        #pragma unroll
        for (int kk = 0; kk < 16; kk++) {
            uint32_t a[4], b[4];
            ldsm_x4(a[0], a[1], a[2], a[3], aBase + kk * 32);
            ldsm_x4(b[0], b[1], b[2], b[3],
                    kb + (uint32_t)(((sni * 16 + brow) * KLD + kk * 16 + bcol8) * 2));
            mma_bf16(d[0], a, b);
            mma_bf16(d[1], a, b + 2);
        }

        // ---- e = exp(s*scale); w = e*mask; masks loaded inline
        bool diagTile = (j == diag_j);
        #pragma unroll
        for (int f = 0; f < 2; f++) {
            int n = sni * 16 + f * 8 + c2;
            float e0 = __expf(d[f][0] * SCALE);
            float e1 = __expf(d[f][1] * SCALE);
            float e2 = __expf(d[f][2] * SCALE);
            float e3 = __expf(d[f][3] * SCALE);
            zacc0 += e0 + e1;
            zacc1 += e2 + e3;
            bool b00, b01, b10, b11;
            if (src == 1) {
                uint64_t bt0 = *(const uint64_t*)(br0 + j * 2);
                uint64_t bt1 = *(const uint64_t*)(br1 + j * 2);
                b00 = (bt0 >> n) & 1;  b01 = (bt0 >> (n + 1)) & 1;
                b10 = (bt1 >> n) & 1;  b11 = (bt1 >> (n + 1)) & 1;
            } else {
                int2 ma = *(const int2*)(mr0 + j * 64 + f * 8);
                int2 mb = *(const int2*)(mr1 + j * 64 + f * 8);
                b00 = ma.x != 0;  b01 = ma.y != 0;
                b10 = mb.x != 0;  b11 = mb.y != 0;
            }
            if (diagTile) {
                if (m0 == n)         { g_eii[i0 + m0]     = b00 ? e0 : 0.f; b00 = false; }
                if (m0 == n + 1)     { g_eii[i0 + m0]     = b01 ? e1 : 0.f; b01 = false; }
                if (m0 + 8 == n)     { g_eii[i0 + m0 + 8] = b10 ? e2 : 0.f; b10 = false; }
                if (m0 + 8 == n + 1) { g_eii[i0 + m0 + 8] = b11 ? e3 : 0.f; b11 = false; }
            }
            float w0 = b00 ? e0 : 0.f, w1 = b01 ? e1 : 0.f;
            float w2 = b10 ? e2 : 0.f, w3 = b11 ? e3 : 0.f;
            t1acc0 += w0 + w1;
            t1acc1 += w2 + w3;
            *(__nv_bfloat162*)(sUp + m0 * ULD + n)       = __floats2bfloat162_rn(w0, w1);
            *(__nv_bfloat162*)(sUp + (m0 + 8) * ULD + n) = __floats2bfloat162_rn(w2, w3);
        }
        __syncthreads();

        // ---- T1 += W @ V: warp m32 x n32 (subset of proven path)
        #pragma unroll
        for (int kk = 0; kk < 4; kk++) {
            uint32_t bv[8];
            ldsm_x4_t(bv[0], bv[1], bv[2], bv[3],
                      kb + (uint32_t)(((kk * 16 + lr16) * KLD + pni * 32 + lc8) * 2));
            ldsm_x4_t(bv[4], bv[5], bv[6], bv[7],
                      kb + (uint32_t)(((kk * 16 + lr16) * KLD + pni * 32 + 16 + lc8) * 2));
            #pragma unroll
            for (int ms = 0; ms < 2; ms++) {
                uint32_t a[4];
                ldsm_x4(a[0], a[1], a[2], a[3],
                        sUo + (uint32_t)(((pmi * 32 + ms * 16 + lr16) * ULD + kk * 16 + lc8) * 2));
                mma_bf16(acc[ms * 4 + 0], a, bv);
                mma_bf16(acc[ms * 4 + 1], a, bv + 2);
                mma_bf16(acc[ms * 4 + 2], a, bv + 4);
                mma_bf16(acc[ms * 4 + 3], a, bv + 6);
            }
        }
        __syncthreads();

        // ---- refill buffer (j&1) with tile j+2
        if (j + 2 < NT) {
            const char* gk = (const char*)(g_kv + (long)(kvrow0 + (j + 2) * KT) * D);
            uint32_t dst = sb + K_OFF + (j & 1) * K_SZ;
            #pragma unroll
            for (int i = 0; i < 4; i++) {
                int idx = tid + i * NTH;
                int k = idx >> 5, cc = (idx & 31) << 3;
                cp16(dst + (uint32_t)((k * KLD + cc) * 2), gk + ((long)k * D + cc) * 2);
            }
        }
        CP_COMMIT();
    }

    // ---- row partials: Z and t1 (quad reduce over n16 window, then atomics;
    //      4 sni-warps contribute per row)
    zacc0 += __shfl_xor_sync(~0u, zacc0, 1); zacc0 += __shfl_xor_sync(~0u, zacc0, 2);
    zacc1 += __shfl_xor_sync(~0u, zacc1, 1); zacc1 += __shfl_xor_sync(~0u, zacc1, 2);
    t1acc0 += __shfl_xor_sync(~0u, t1acc0, 1); t1acc0 += __shfl_xor_sync(~0u, t1acc0, 2);
    t1acc1 += __shfl_xor_sync(~0u, t1acc1, 1); t1acc1 += __shfl_xor_sync(~0u, t1acc1, 2);
    if ((lane & 3) == 0) {
        atomicAdd(&g_Z[src * 8192 + i0 + m0],      zacc0);
        atomicAdd(&g_Z[src * 8192 + i0 + m0 + 8],  zacc1);
        atomicAdd(&g_t1[src * 8192 + i0 + m0],     t1acc0);
        atomicAdd(&g_t1[src * 8192 + i0 + m0 + 8], t1acc1);
    }

    // ---- T1 partial atomics (unscaled; finalize applies 1/Z)
    #pragma unroll
    for (int ms = 0; ms < 2; ms++) {
        long b0 = ((long)src * 8192 + i0 + pmi * 32 + ms * 16 + g) * 256;
        #pragma unroll
        for (int f = 0; f < 4; f++) {
            int col = pni * 32 + f * 8 + c2;
            float* ac = acc[ms * 4 + f];
            atomicAdd(&g_T1[b0 + col],               ac[0]);
            atomicAdd(&g_T1[b0 + col + 1],           ac[1]);
            atomicAdd(&g_T1[b0 + 8 * 256 + col],     ac[2]);
            atomicAdd(&g_T1[b0 + 8 * 256 + col + 1], ac[3]);
        }
    }
}

// ---------------------------------------------------------------------------
__global__ void finalize_kernel(float* __restrict__ out) {
    int i = blockIdx.x, c = threadIdx.x;
    float rz0 = 1.0f / g_Z[i];
    float rz1 = 1.0f / g_Z[8192 + i];
    float rz2 = 1.0f / g_Z[16384 + i];

    float s = g_eii[i];
    float u = (s > 0.f) ? (__expf(s * rz0) - 1.0f) : 0.0f;
    float v = __bfloat162float(g_kv[(long)i * 256 + c]);

    float n0 = g_vsum[c]       + g_T1[((long)0 * 8192 + i) * 256 + c] * rz0 + u * v;
    float d0 = 8192.0f  + g_t1[i] * rz0 + u;
    float n1 = g_vsum[256 + c] + g_T1[((long)1 * 8192 + i) * 256 + c] * rz1;
    float d1 = 4096.0f  + g_t1[8192 + i] * rz1;
    float n2 = g_vsum[512 + c] + g_T1[((long)2 * 8192 + i) * 256 + c] * rz2;
    float d2 = 16384.0f + g_t1[16384 + i] * rz2;

    out[(long)i * 256 + c] = (n0 / d0 + n1 / d1 + n2 / d2) * (1.0f / 3.0f);
}

// ---------------------------------------------------------------------------
extern "C" void kernel_launch(void* const* d_in, const int* in_sizes, int n_in,
                              void* d_out, int out_size) {
    const int*   L     = (const int*)d_in[0];
    const float* H     = (const float*)d_in[1];
    const int*   Blow  = (const int*)d_in[2];
    const float* Hlow  = (const float*)d_in[3];
    const int*   Bhigh = (const int*)d_in[4];
    const float* Hhigh = (const float*)d_in[5];
    float* out = (float*)d_out;

    cudaFuncSetAttribute(attn_kernel,
                         cudaFuncAttributeMaxDynamicSharedMemorySize, SMEM_TOTAL);

    init_kernel<<<24576, 256>>>();
    convert_kernel<<<896, 256>>>(H, Hlow, Hhigh);
    pack_T_kernel<<<32768, 256>>>(Blow);
    attn_kernel<<<896, NTH, SMEM_TOTAL>>>(L, Bhigh);
    finalize_kernel<<<8192, 256>>>(out);
}

// round 14
// speedup vs baseline: 1.5280x; 1.5280x over previous
#include <cuda_runtime.h>
#include <cuda_bf16.h>
#include <cstdint>

// ============================================================================
// Simplicial attention, single-pass linearized, wave-balanced 888-CTA grid.
// Per source (K=V):
//   Z_i = sum_j exp(s_ij)         (unmasked)
//   u_ij ~= (e_ij/Z_i) m_ij       (order-1; src0 diagonal exact via expm1)
//   out_i = sum_src (colsum(V) + T1_i/Z_i + u_ii v_i)/(M + t1_i/Z_i + u_ii)/3
// Work space flattened to 57344 key-tiles; 888 CTAs (= 296 slots x 3 exact
// waves) each take a contiguous 64-65 tile slice (<= 2 segments).
// Compute core byte-identical to the proven R11 kernel.
// ============================================================================

#define D      256
#define QR     64
#define KT     64
#define NT     64
#define NTH    256
#define NQ     8192
#define SCALE  0.0625f
#define QLD    264
#define KLD    264
#define ULD    72

#define NJOBS  57344           // 128 qt x 7 ch x 64 tiles
#define GRID   888             // 148 SMs x 2 CTAs x 3 waves

#define SQ_OFF  0
#define SQ_SZ   (QR * QLD * 2)            // 33792
#define K_OFF   SQ_SZ
#define K_SZ    (KT * KLD * 2)            // 33792 x2
#define U_OFF   (K_OFF + 2 * K_SZ)        // 101376
#define U_SZ    (QR * ULD * 2)            // 9216
#define SMEM_TOTAL (U_OFF + U_SZ)         // 110592 -> 2 CTAs/SM

// ---------------------------------------------------------------------------
__device__ __align__(128) __nv_bfloat16 g_kv[28672 * 256];   // 14.7 MB
__device__ __align__(128) float    g_vsum[3 * 256];
__device__ __align__(128) uint32_t g_mb1[8192L * 128];       // 4 MB, B_low^T bits
__device__ __align__(128) float    g_T1[3L * 8192 * 256];    // 25 MB partials
__device__ __align__(128) float    g_Z[3 * 8192];
__device__ __align__(128) float    g_t1[3 * 8192];
__device__ __align__(128) float    g_eii[8192];              // masked diag e

__device__ __forceinline__ uint32_t smem_u32(const void* p) {
    return (uint32_t)__cvta_generic_to_shared(p);
}
__device__ __forceinline__ void cp16(uint32_t dst, const void* src) {
    asm volatile("cp.async.cg.shared.global [%0], [%1], 16;" :: "r"(dst), "l"(src));
}
#define CP_COMMIT() asm volatile("cp.async.commit_group;" ::: "memory")
#define CP_WAIT1()  asm volatile("cp.async.wait_group 1;" ::: "memory")

__device__ __forceinline__ void ldsm_x4(uint32_t& r0, uint32_t& r1,
                                        uint32_t& r2, uint32_t& r3, uint32_t addr) {
    asm volatile("ldmatrix.sync.aligned.m8n8.x4.shared.b16 {%0,%1,%2,%3}, [%4];\n"
                 : "=r"(r0), "=r"(r1), "=r"(r2), "=r"(r3) : "r"(addr));
}
__device__ __forceinline__ void ldsm_x4_t(uint32_t& r0, uint32_t& r1,
                                          uint32_t& r2, uint32_t& r3, uint32_t addr) {
    asm volatile("ldmatrix.sync.aligned.m8n8.x4.trans.shared.b16 {%0,%1,%2,%3}, [%4];\n"
                 : "=r"(r0), "=r"(r1), "=r"(r2), "=r"(r3) : "r"(addr));
}
__device__ __forceinline__ void mma_bf16(float* d, const uint32_t* a, const uint32_t* b) {
    asm volatile(
        "mma.sync.aligned.m16n8k16.row.col.f32.bf16.bf16.f32 "
        "{%0,%1,%2,%3}, {%4,%5,%6,%7}, {%8,%9}, {%0,%1,%2,%3};\n"
        : "+f"(d[0]), "+f"(d[1]), "+f"(d[2]), "+f"(d[3])
        : "r"(a[0]), "r"(a[1]), "r"(a[2]), "r"(a[3]), "r"(b[0]), "r"(b[1]));
}

// ---------------------------------------------------------------------------
__global__ void init_kernel() {
    long idx = (long)blockIdx.x * 256 + threadIdx.x;
    if (idx < 3L * 8192 * 256) g_T1[idx] = 0.0f;
    if (idx < 3 * 8192) { g_Z[idx] = 0.0f; g_t1[idx] = 0.0f; }
    if (idx < 8192) g_eii[idx] = 0.0f;
    if (idx < 3 * 256) g_vsum[idx] = 0.0f;
}

__global__ void convert_kernel(const float* __restrict__ H,
                               const float* __restrict__ Hlow,
                               const float* __restrict__ Hhigh) {
    int r0 = blockIdx.x * 32, col = threadIdx.x;
    float acc = 0.0f;
    #pragma unroll 4
    for (int i = 0; i < 32; i++) {
        int r = r0 + i;
        float v;
        if (r < 8192)       v = H[(long)r * D + col];
        else if (r < 12288) v = Hlow[(long)(r - 8192) * D + col];
        else                v = Hhigh[(long)(r - 12288) * D + col];
        g_kv[(long)r * D + col] = __float2bfloat16(v);
        acc += v;
    }
    int src = (r0 < 8192) ? 0 : (r0 < 12288 ? 1 : 2);
    atomicAdd(&g_vsum[src * 256 + col], acc);
}

// pack B_low[4096][8192] transposed -> g_mb1[8192 rows][128 words]
__global__ void pack_T_kernel(const int* __restrict__ B) {
    __shared__ int sm[32 * 33];
    int kt = blockIdx.x & 127, it = blockIdx.x >> 7;
    int k0 = kt * 32, i0 = it * 32;
    int tid = threadIdx.x;
    #pragma unroll
    for (int s = 0; s < 4; s++) {
        int idx = tid + s * 256;
        int r = idx >> 5, c = idx & 31;
        sm[r * 33 + c] = B[(long)(k0 + r) * NQ + i0 + c];
    }
    __syncthreads();
    int w = tid >> 5, lane = tid & 31;
    #pragma unroll
    for (int q = 0; q < 4; q++) {
        int i = w * 4 + q;
        uint32_t word = __ballot_sync(0xffffffffu, sm[lane * 33 + i] != 0);
        if (lane == 0) g_mb1[(long)(i0 + i) * 128 + kt] = word;
    }
}

// ---------------------------------------------------------------------------
__global__ __launch_bounds__(NTH, 2)
void attn_kernel(const int* __restrict__ L,
                 const int* __restrict__ Bhigh) {
    extern __shared__ char smem[];
    uint32_t sb = smem_u32(smem);
    const uint32_t sQ = sb + SQ_OFF;
    __nv_bfloat16* sUp = (__nv_bfloat16*)(smem + U_OFF);

    int tid = threadIdx.x, lane = tid & 31, w = tid >> 5;
    int mi = w & 3, ni = w >> 2;
    int g = lane >> 2, c2 = (lane & 3) << 1;
    int lr16 = lane & 15, lc8 = (lane >> 4) << 3;
    int brow = (lane & 7) + ((lane & 16) >> 1), bcol8 = lane & 8;
    int m0 = mi * 16 + g;
    int wn = w * 32;

    // contiguous tile slice [t, tend)
    int t    = (int)(((long)blockIdx.x * NJOBS) / GRID);
    int tend = (int)(((long)(blockIdx.x + 1) * NJOBS) / GRID);

    while (t < tend) {
        int qt = t / 448;
        int rem = t - qt * 448;
        int ch = rem >> 6;
        int j0 = rem & 63;
        int len = 64 - j0;
        if (len > tend - t) len = tend - t;
        int jEnd = j0 + len;
        int i0 = qt * QR;

        int src, kvrow0, kloc0, W;
        const int* mask;
        if (ch < 2)      { src = 0; kvrow0 = ch * 4096;            kloc0 = ch * 4096;     W = 8192;  mask = L; }
        else if (ch == 2){ src = 1; kvrow0 = 8192;                 kloc0 = 0;             W = 0;     mask = L; }
        else             { src = 2; kvrow0 = 12288 + (ch-3)*4096;  kloc0 = (ch-3)*4096;   W = 16384; mask = Bhigh; }
        int diag_j = -1;
        if (src == 0) { int dj = (i0 - kloc0) >> 6; if (dj >= 0 && dj < NT) diag_j = dj; }

        // ---- prologue: Q + K(j0) group, K(j0+1) group
        {
            const char* gq = (const char*)(g_kv + (long)i0 * D);
            #pragma unroll
            for (int i = 0; i < 8; i++) {
                int idx = tid + i * NTH;
                int r = idx >> 5, cc = (idx & 31) << 3;
                cp16(sQ + (uint32_t)((r * QLD + cc) * 2), gq + ((long)r * D + cc) * 2);
            }
            const char* gk = (const char*)(g_kv + (long)(kvrow0 + j0 * KT) * D);
            #pragma unroll
            for (int i = 0; i < 8; i++) {
                int idx = tid + i * NTH;
                int k = idx >> 5, cc = (idx & 31) << 3;
                cp16(sb + K_OFF + (uint32_t)(j0 & 1) * K_SZ
                        + (uint32_t)((k * KLD + cc) * 2), gk + ((long)k * D + cc) * 2);
            }
            CP_COMMIT();
            if (len > 1) {
                const char* gk1 = (const char*)(g_kv + (long)(kvrow0 + (j0 + 1) * KT) * D);
                #pragma unroll
                for (int i = 0; i < 8; i++) {
                    int idx = tid + i * NTH;
                    int k = idx >> 5, cc = (idx & 31) << 3;
                    cp16(sb + K_OFF + (uint32_t)((j0 + 1) & 1) * K_SZ
                            + (uint32_t)((k * KLD + cc) * 2), gk1 + ((long)k * D + cc) * 2);
                }
            }
            CP_COMMIT();
        }

        float zacc0 = 0.f, zacc1 = 0.f, t1acc0 = 0.f, t1acc1 = 0.f;
        float acc[16][4];
        #pragma unroll
        for (int f = 0; f < 16; f++) { acc[f][0]=0.f; acc[f][1]=0.f; acc[f][2]=0.f; acc[f][3]=0.f; }

        uint32_t aBase = sQ + (uint32_t)(((mi * 16 + lr16) * QLD + lc8) * 2);
        uint32_t sUo = sb + U_OFF;
        const int* mr0 = mask + (long)(i0 + m0) * W + kloc0 + ni * 32 + c2;
        const int* mr1 = mask + (long)(i0 + m0 + 8) * W + kloc0 + ni * 32 + c2;
        const uint32_t* br0 = g_mb1 + (long)(i0 + m0) * 128;
        const uint32_t* br1 = g_mb1 + (long)(i0 + m0 + 8) * 128;

        for (int j = j0; j < jEnd; j++) {
            CP_WAIT1();
            __syncthreads();
            uint32_t kb = sb + K_OFF + (j & 1) * K_SZ;

            // ---- mask loads (early; overlap S-GEMM)
            int2 ma[4], mb[4];
            uint64_t bt0 = 0, bt1 = 0;
            if (src == 1) {
                bt0 = *(const uint64_t*)(br0 + j * 2);
                bt1 = *(const uint64_t*)(br1 + j * 2);
            } else {
                #pragma unroll
                for (int f = 0; f < 4; f++) {
                    ma[f] = *(const int2*)(mr0 + j * 64 + f * 8);
                    mb[f] = *(const int2*)(mr1 + j * 64 + f * 8);
                }
            }

            // ---- S = Q K^T (64x64), proven fragment path
            float d[4][4];
            #pragma unroll
            for (int f = 0; f < 4; f++) { d[f][0]=0.f; d[f][1]=0.f; d[f][2]=0.f; d[f][3]=0.f; }
            #pragma unroll
            for (int kk = 0; kk < 16; kk++) {
                uint32_t a[4];
                ldsm_x4(a[0], a[1], a[2], a[3], aBase + kk * 32);
                #pragma unroll
                for (int jj = 0; jj < 2; jj++) {
                    uint32_t b[4];
                    uint32_t ba = kb + (uint32_t)(((ni * 32 + jj * 16 + brow) * KLD
                                                   + kk * 16 + bcol8) * 2);
                    ldsm_x4(b[0], b[1], b[2], b[3], ba);
                    mma_bf16(d[2 * jj],     a, b);
                    mma_bf16(d[2 * jj + 1], a, b + 2);
                }
            }

            // ---- e = exp(s*scale); w = e*mask; stash masked diag e (src0)
            bool diagTile = (j == diag_j);
            #pragma unroll
            for (int f = 0; f < 4; f++) {
                int n = ni * 32 + f * 8 + c2;
                float e0 = __expf(d[f][0] * SCALE);
                float e1 = __expf(d[f][1] * SCALE);
                float e2 = __expf(d[f][2] * SCALE);
                float e3 = __expf(d[f][3] * SCALE);
                zacc0 += e0 + e1;
                zacc1 += e2 + e3;
                bool b00, b01, b10, b11;
                if (src == 1) {
                    b00 = (bt0 >> n) & 1;  b01 = (bt0 >> (n + 1)) & 1;
                    b10 = (bt1 >> n) & 1;  b11 = (bt1 >> (n + 1)) & 1;
                } else {
                    b00 = ma[f].x != 0;  b01 = ma[f].y != 0;
                    b10 = mb[f].x != 0;  b11 = mb[f].y != 0;
                }
                if (diagTile) {
                    if (m0 == n)         { g_eii[i0 + m0]     = b00 ? e0 : 0.f; b00 = false; }
                    if (m0 == n + 1)     { g_eii[i0 + m0]     = b01 ? e1 : 0.f; b01 = false; }
                    if (m0 + 8 == n)     { g_eii[i0 + m0 + 8] = b10 ? e2 : 0.f; b10 = false; }
                    if (m0 + 8 == n + 1) { g_eii[i0 + m0 + 8] = b11 ? e3 : 0.f; b11 = false; }
                }
                float w0 = b00 ? e0 : 0.f, w1 = b01 ? e1 : 0.f;
                float w2 = b10 ? e2 : 0.f, w3 = b11 ? e3 : 0.f;
                t1acc0 += w0 + w1;
                t1acc1 += w2 + w3;
                *(__nv_bfloat162*)(sUp + m0 * ULD + n)       = __floats2bfloat162_rn(w0, w1);
                *(__nv_bfloat162*)(sUp + (m0 + 8) * ULD + n) = __floats2bfloat162_rn(w2, w3);
            }
            __syncthreads();

            // ---- T1 += W @ V: warp owns all 64 rows x 32 cols
            #pragma unroll
            for (int kk = 0; kk < 4; kk++) {
                uint32_t bv[8];
                ldsm_x4_t(bv[0], bv[1], bv[2], bv[3],
                          kb + (uint32_t)(((kk * 16 + lr16) * KLD + wn + lc8) * 2));
                ldsm_x4_t(bv[4], bv[5], bv[6], bv[7],
                          kb + (uint32_t)(((kk * 16 + lr16) * KLD + wn + 16 + lc8) * 2));
                #pragma unroll
                for (int ms = 0; ms < 4; ms++) {
                    uint32_t a[4];
                    ldsm_x4(a[0], a[1], a[2], a[3],
                            sUo + (uint32_t)(((ms * 16 + lr16) * ULD + kk * 16 + lc8) * 2));
                    mma_bf16(acc[ms * 4 + 0], a, bv);
                    mma_bf16(acc[ms * 4 + 1], a, bv + 2);
                    mma_bf16(acc[ms * 4 + 2], a, bv + 4);
                    mma_bf16(acc[ms * 4 + 3], a, bv + 6);
                }
            }
            __syncthreads();

            // ---- refill buffer (j&1) with tile j+2
            if (j + 2 < jEnd) {
                const char* gk = (const char*)(g_kv + (long)(kvrow0 + (j + 2) * KT) * D);
                uint32_t dst = sb + K_OFF + (uint32_t)(j & 1) * K_SZ;
                #pragma unroll
                for (int i = 0; i < 8; i++) {
                    int idx = tid + i * NTH;
                    int k = idx >> 5, cc = (idx & 31) << 3;
                    cp16(dst + (uint32_t)((k * KLD + cc) * 2), gk + ((long)k * D + cc) * 2);
                }
            }
            CP_COMMIT();
        }

        // ---- row partials: Z and t1 (quad reduce, then global atomics)
        zacc0 += __shfl_xor_sync(~0u, zacc0, 1); zacc0 += __shfl_xor_sync(~0u, zacc0, 2);
        zacc1 += __shfl_xor_sync(~0u, zacc1, 1); zacc1 += __shfl_xor_sync(~0u, zacc1, 2);
        t1acc0 += __shfl_xor_sync(~0u, t1acc0, 1); t1acc0 += __shfl_xor_sync(~0u, t1acc0, 2);
        t1acc1 += __shfl_xor_sync(~0u, t1acc1, 1); t1acc1 += __shfl_xor_sync(~0u, t1acc1, 2);
        if ((lane & 3) == 0) {
            atomicAdd(&g_Z[src * 8192 + i0 + m0],      zacc0);
            atomicAdd(&g_Z[src * 8192 + i0 + m0 + 8],  zacc1);
            atomicAdd(&g_t1[src * 8192 + i0 + m0],     t1acc0);
            atomicAdd(&g_t1[src * 8192 + i0 + m0 + 8], t1acc1);
        }

        // ---- T1 partial atomics (unscaled; finalize applies 1/Z)
        #pragma unroll
        for (int ms = 0; ms < 4; ms++) {
            long b0 = ((long)src * 8192 + i0 + ms * 16 + g) * 256;
            #pragma unroll
            for (int f = 0; f < 4; f++) {
                int col = wn + f * 8 + c2;
                float* ac = acc[ms * 4 + f];
                atomicAdd(&g_T1[b0 + col],               ac[0]);
                atomicAdd(&g_T1[b0 + col + 1],           ac[1]);
                atomicAdd(&g_T1[b0 + 8 * 256 + col],     ac[2]);
                atomicAdd(&g_T1[b0 + 8 * 256 + col + 1], ac[3]);
            }
        }

        t += len;
        __syncthreads();   // all smem reads done before next segment's prologue
    }
}

// ---------------------------------------------------------------------------
__global__ void finalize_kernel(float* __restrict__ out) {
    int i = blockIdx.x, c = threadIdx.x;
    float rz0 = 1.0f / g_Z[i];
    float rz1 = 1.0f / g_Z[8192 + i];
    float rz2 = 1.0f / g_Z[16384 + i];

    float s = g_eii[i];
    float u = (s > 0.f) ? (__expf(s * rz0) - 1.0f) : 0.0f;
    float v = __bfloat162float(g_kv[(long)i * 256 + c]);

    float n0 = g_vsum[c]       + g_T1[((long)0 * 8192 + i) * 256 + c] * rz0 + u * v;
    float d0 = 8192.0f  + g_t1[i] * rz0 + u;
    float n1 = g_vsum[256 + c] + g_T1[((long)1 * 8192 + i) * 256 + c] * rz1;
    float d1 = 4096.0f  + g_t1[8192 + i] * rz1;
    float n2 = g_vsum[512 + c] + g_T1[((long)2 * 8192 + i) * 256 + c] * rz2;
    float d2 = 16384.0f + g_t1[16384 + i] * rz2;

    out[(long)i * 256 + c] = (n0 / d0 + n1 / d1 + n2 / d2) * (1.0f / 3.0f);
}

// ---------------------------------------------------------------------------
extern "C" void kernel_launch(void* const* d_in, const int* in_sizes, int n_in,
                              void* d_out, int out_size) {
    const int*   L     = (const int*)d_in[0];
    const float* H     = (const float*)d_in[1];
    const int*   Blow  = (const int*)d_in[2];
    const float* Hlow  = (const float*)d_in[3];
    const int*   Bhigh = (const int*)d_in[4];
    const float* Hhigh = (const float*)d_in[5];
    float* out = (float*)d_out;

    cudaFuncSetAttribute(attn_kernel,
                         cudaFuncAttributeMaxDynamicSharedMemorySize, SMEM_TOTAL);

    init_kernel<<<24576, 256>>>();
    convert_kernel<<<896, 256>>>(H, Hlow, Hhigh);
    pack_T_kernel<<<32768, 256>>>(Blow);
    attn_kernel<<<GRID, NTH, SMEM_TOTAL>>>(L, Bhigh);
    finalize_kernel<<<8192, 256>>>(out);
}